// round 2
// baseline (speedup 1.0000x reference)
#include <cuda_runtime.h>

#define BATCH 32
#define CIN   64
#define COUT  64
#define HW    64
#define PLANE (HW * HW)        // 4096
#define KK    9
#define WSMEM (CIN * KK * COUT)  // 36864 floats = 147456 bytes

// Scratch: deform-conv output + per-(b,o) reduction stats.
__device__ float g_d[BATCH * COUT * PLANE];   // ~33.5 MB
__device__ float g_sum[BATCH * COUT];
__device__ float g_sqs[BATCH * COUT];

__global__ void zero_stats_kernel() {
    int i = blockIdx.x * blockDim.x + threadIdx.x;
    if (i < BATCH * COUT) { g_sum[i] = 0.f; g_sqs[i] = 0.f; }
}

__global__ __launch_bounds__(512, 1)
void deform_kernel(const float* __restrict__ x,
                   const float* __restrict__ offset,
                   const float* __restrict__ weight)
{
    extern __shared__ float w_sh[];  // [c][k][o] layout: (c*9+k)*64 + o

    // Cooperative reorder of weight [o][c][k] -> smem [c][k][o].
    // Global reads coalesced; smem write conflicts are negligible one-time cost.
    for (int idx = threadIdx.x; idx < COUT * CIN * KK; idx += blockDim.x) {
        int o  = idx / (CIN * KK);
        int ck = idx % (CIN * KK);
        w_sh[ck * COUT + o] = weight[idx];
    }
    __syncthreads();

    const int b    = blockIdx.x >> 3;
    const int rowg = blockIdx.x & 7;
    const int tid  = threadIdx.x;
    const int row  = rowg * 8 + (tid >> 6);
    const int col  = tid & 63;
    const int pix  = row * HW + col;

    const float* xb   = x + (size_t)b * CIN * PLANE;
    const float* offb = offset + (size_t)b * (2 * KK) * PLANE + pix;

    // 64 fp32 accumulators packed as 32 f32x2
    unsigned long long acc2[32];
    #pragma unroll
    for (int i = 0; i < 32; i++) acc2[i] = 0ull;

    #pragma unroll 1
    for (int k = 0; k < KK; k++) {
        const int ky = k / 3;
        const int kx = k - 3 * ky;
        const float oy = __ldg(offb + (2 * k) * PLANE);
        const float ox = __ldg(offb + (2 * k + 1) * PLANE);
        const float py = (float)(row - 1 + ky) + oy;
        const float px = (float)(col - 1 + kx) + ox;
        const float y0f = floorf(py), x0f = floorf(px);
        const float fy = py - y0f,  fx = px - x0f;
        const int y0 = (int)y0f, x0 = (int)x0f;
        const int y1 = y0 + 1,   x1 = x0 + 1;
        const float vy0 = (y0 >= 0 && y0 < HW) ? 1.f : 0.f;
        const float vy1 = (y1 >= 0 && y1 < HW) ? 1.f : 0.f;
        const float vx0 = (x0 >= 0 && x0 < HW) ? 1.f : 0.f;
        const float vx1 = (x1 >= 0 && x1 < HW) ? 1.f : 0.f;
        const int cy0 = min(max(y0, 0), HW - 1), cy1 = min(max(y1, 0), HW - 1);
        const int cx0 = min(max(x0, 0), HW - 1), cx1 = min(max(x1, 0), HW - 1);
        const float w00 = (1.f - fy) * (1.f - fx) * vy0 * vx0;
        const float w01 = (1.f - fy) * fx        * vy0 * vx1;
        const float w10 = fy        * (1.f - fx) * vy1 * vx0;
        const float w11 = fy        * fx         * vy1 * vx1;
        const int i00 = cy0 * HW + cx0, i01 = cy0 * HW + cx1;
        const int i10 = cy1 * HW + cx0, i11 = cy1 * HW + cx1;

        // smem row base for this k, in ulonglong2 units handled below
        const unsigned long long* wk =
            reinterpret_cast<const unsigned long long*>(w_sh) + (size_t)k * 32;

        #pragma unroll 2
        for (int c = 0; c < CIN; c++) {
            const float* p = xb + c * PLANE;
            float s = w00 * __ldg(p + i00) + w01 * __ldg(p + i01)
                    + w10 * __ldg(p + i10) + w11 * __ldg(p + i11);
            unsigned long long s2;
            asm("mov.b64 %0, {%1, %1};" : "=l"(s2) : "f"(s));
            const ulonglong2* wc =
                reinterpret_cast<const ulonglong2*>(wk + (size_t)c * (KK * 32));
            #pragma unroll
            for (int i = 0; i < 16; i++) {
                ulonglong2 wv = wc[i];
                asm("fma.rn.f32x2 %0, %1, %2, %0;"
                    : "+l"(acc2[2 * i])     : "l"(s2), "l"(wv.x));
                asm("fma.rn.f32x2 %0, %1, %2, %0;"
                    : "+l"(acc2[2 * i + 1]) : "l"(s2), "l"(wv.y));
            }
        }
    }

    // Write d + warp-reduce stats
    const size_t dbase = (size_t)b * COUT * PLANE + pix;
    #pragma unroll 1
    for (int i = 0; i < 32; i++) {
        float a0 = __uint_as_float((unsigned)(acc2[i] & 0xffffffffull));
        float a1 = __uint_as_float((unsigned)(acc2[i] >> 32));
        g_d[dbase + (size_t)(2 * i)     * PLANE] = a0;
        g_d[dbase + (size_t)(2 * i + 1) * PLANE] = a1;
        float s0 = a0, q0 = a0 * a0, s1 = a1, q1 = a1 * a1;
        #pragma unroll
        for (int d = 16; d > 0; d >>= 1) {
            s0 += __shfl_xor_sync(0xffffffffu, s0, d);
            q0 += __shfl_xor_sync(0xffffffffu, q0, d);
            s1 += __shfl_xor_sync(0xffffffffu, s1, d);
            q1 += __shfl_xor_sync(0xffffffffu, q1, d);
        }
        if ((threadIdx.x & 31) == 0) {
            atomicAdd(&g_sum[b * COUT + 2 * i],     s0);
            atomicAdd(&g_sqs[b * COUT + 2 * i],     q0);
            atomicAdd(&g_sum[b * COUT + 2 * i + 1], s1);
            atomicAdd(&g_sqs[b * COUT + 2 * i + 1], q1);
        }
    }
}

__global__ void norm_kernel(const float* __restrict__ gamma_p,
                            const float* __restrict__ beta_p,
                            float* __restrict__ out)
{
    const int bo = blockIdx.x;  // b*COUT + o
    const float sum = g_sum[bo];
    const float sqs = g_sqs[bo];
    const float n = (float)PLANE;
    const float mu = sum / n;
    float var = (sqs - sum * sum / n) / (n - 1.f);
    var = fmaxf(var, 0.f);
    const float sd = sqrtf(var);
    const float gamma = __ldg(gamma_p);
    const float beta  = __ldg(beta_p);
    const float scale = gamma / (sd + 1e-8f);

    const float4* dsrc = reinterpret_cast<const float4*>(g_d + (size_t)bo * PLANE);
    float4* o = reinterpret_cast<float4*>(out + (size_t)bo * PLANE);
    for (int i = threadIdx.x; i < PLANE / 4; i += blockDim.x) {
        float4 v = dsrc[i];
        float4 r;
        r.x = tanhf((v.x - mu) * scale + beta);
        r.y = tanhf((v.y - mu) * scale + beta);
        r.z = tanhf((v.z - mu) * scale + beta);
        r.w = tanhf((v.w - mu) * scale + beta);
        o[i] = r;
    }
}

extern "C" void kernel_launch(void* const* d_in, const int* in_sizes, int n_in,
                              void* d_out, int out_size)
{
    const float* x      = (const float*)d_in[0];
    const float* offset = (const float*)d_in[1];
    const float* weight = (const float*)d_in[2];
    const float* gamma  = (const float*)d_in[3];
    const float* beta   = (const float*)d_in[4];

    cudaFuncSetAttribute(deform_kernel,
                         cudaFuncAttributeMaxDynamicSharedMemorySize,
                         WSMEM * (int)sizeof(float));

    zero_stats_kernel<<<4, 512>>>();
    deform_kernel<<<(BATCH * PLANE) / 512, 512, WSMEM * sizeof(float)>>>(x, offset, weight);
    norm_kernel<<<BATCH * COUT, 256>>>(gamma, beta, (float*)d_out);
}